// round 16
// baseline (speedup 1.0000x reference)
#include <cuda_runtime.h>
#include <math.h>

// Problem dims (fixed by the reference)
#define BATCH 16
#define NQ    500   // queries (pred) = columns
#define NT    128   // targets       = rows
#define KPT   34    // 17 keypoints * 2
#define NCPL  16    // ARR: columns per lane (single warp)
#define NCPT  4     // Dijkstra: columns per thread (128 threads)
#define QT    4     // queries per cost block (500 = 125 * 4)

// Transposed cost scratch: [b][target n][query q], f32 only.
__device__ float g_ct[BATCH * NT * NQ];

// ---------------------------------------------------------------------------
// Kernel 1: cost matrix (passing R14/R15 version, unchanged).
// ---------------------------------------------------------------------------
__global__ __launch_bounds__(128) void cost_kernel(
    const float* __restrict__ pred_boxes,   // (B, Q, 4)  cxcywh
    const float* __restrict__ pred_kpts,    // (B, Q, 17, 2)
    const float* __restrict__ tgt_boxes,    // (B, N, 4)  cxcywh
    const float* __restrict__ tgt_kpts,     // (B, N, 17, 2)
    float* __restrict__ C)                  // (B, Q, N)
{
    const int q0 = blockIdx.x * QT;
    const int b  = blockIdx.y;
    const int n  = threadIdx.x;

    __shared__ float s_pk[QT][KPT];
    __shared__ float s_pb[QT][4];
    for (int x = n; x < QT * KPT; x += 128)
        s_pk[x / KPT][x % KPT] = pred_kpts[(size_t)(b * NQ + q0 + x / KPT) * KPT + (x % KPT)];
    if (n < QT * 4)
        s_pb[n >> 2][n & 3] = pred_boxes[(b * NQ + q0 + (n >> 2)) * 4 + (n & 3)];
    __syncthreads();

    const float* tbn = tgt_boxes + (b * NT + n) * 4;
    const float t0 = __ldg(tbn + 0), t1 = __ldg(tbn + 1);
    const float t2 = __ldg(tbn + 2), t3 = __ldg(tbn + 3);
    float tx0 = t0 - 0.5f * t2, ty0 = t1 - 0.5f * t3;
    float tx1 = t0 + 0.5f * t2, ty1 = t1 + 0.5f * t3;
    tx1 = fmaxf(tx1, tx0 + 1e-4f);
    ty1 = fmaxf(ty1, ty0 + 1e-4f);
    const float at = (tx1 - tx0) * (ty1 - ty0);

    float tk[KPT];
    {
        const float2* tk2 = (const float2*)(tgt_kpts + (size_t)(b * NT + n) * KPT);
#pragma unroll
        for (int k = 0; k < KPT / 2; k++) {
            const float2 p = __ldg(tk2 + k);
            tk[2 * k] = p.x; tk[2 * k + 1] = p.y;
        }
    }

    float res[QT];
#pragma unroll
    for (int t = 0; t < QT; t++) {
        const float p0 = s_pb[t][0], p1 = s_pb[t][1], p2 = s_pb[t][2], p3 = s_pb[t][3];

        float cbbox = fabsf(p0 - t0) + fabsf(p1 - t1) + fabsf(p2 - t2) + fabsf(p3 - t3);

        float px0 = p0 - 0.5f * p2, py0 = p1 - 0.5f * p3;
        float px1 = p0 + 0.5f * p2, py1 = p1 + 0.5f * p3;
        px1 = fmaxf(px1, px0 + 1e-4f);
        py1 = fmaxf(py1, py0 + 1e-4f);

        const float ap = (px1 - px0) * (py1 - py0);

        const float iw = fmaxf(fminf(px1, tx1) - fmaxf(px0, tx0), 0.0f);
        const float ih = fmaxf(fminf(py1, ty1) - fmaxf(py0, ty0), 0.0f);
        const float inter = iw * ih;
        const float uni = ap + at - inter;
        const float iou = inter / uni;

        const float ew = fmaxf(fmaxf(px1, tx1) - fminf(px0, tx0), 0.0f);
        const float eh = fmaxf(fmaxf(py1, ty1) - fminf(py0, ty0), 0.0f);
        const float enc = ew * eh;
        const float giou = iou - (enc - uni) / enc;

        float ckpt = 0.0f;
#pragma unroll
        for (int k = 0; k < KPT; k++) ckpt += fabsf(s_pk[t][k] - tk[k]);

        const float cost = 5.0f * cbbox - 2.0f * giou + 1.0f * ckpt;
        res[t] = cost;
        C[(size_t)(b * NQ + q0 + t) * NT + n] = cost;
    }
    *(float4*)(g_ct + (size_t)(b * NT + n) * NQ + q0) =
        make_float4(res[0], res[1], res[2], res[3]);
}

// Monotone bijection double <-> uint64 (order-preserving, exact).
__device__ __forceinline__ unsigned long long dkey(double x) {
    const long long b = __double_as_longlong(x);
    return (unsigned long long)b ^ ((b < 0) ? 0xFFFFFFFFFFFFFFFFULL
                                             : 0x8000000000000000ULL);
}
__device__ __forceinline__ double kinv(unsigned long long k) {
    const long long b = (k & 0x8000000000000000ULL)
                      ? (long long)(k ^ 0x8000000000000000ULL)
                      : ~(long long)k;
    return __longlong_as_double(b);
}

// ---------------------------------------------------------------------------
// Kernel 2: exact JV LSA. This round: the Dijkstra sweep runs on ALL 4 warps
// (thread tid owns columns j = k*128 + tid, k<4); per-warp redux argmin, then
// one __syncthreads + deterministic 4-slot merge (same 64-bit key, same
// smaller-j tie-break -> bit-identical column choice and minv to R15).
// Init / greedy / ARR / dual updates / augmentation semantics unchanged.
// ---------------------------------------------------------------------------
__global__ __launch_bounds__(128) void lsa_kernel(float* __restrict__ out, int out_size)
{
    const int b    = blockIdx.x;
    const int tid  = threadIdx.x;
    const int lane = tid & 31;
    const int wid  = tid >> 5;
    const float* __restrict__ ct = g_ct + (size_t)b * NT * NQ;

    __shared__ double v[NQ];
    __shared__ double u[NT];
    __shared__ double cdist[NQ];
    __shared__ ulonglong2 pk[NQ];       // per-phase: {u[row4col[j]] bits, row4col[j]}
    __shared__ int    clist[NQ];
    __shared__ int    path[NQ];
    __shared__ int    row4col[NQ];
    __shared__ int    col4row[NT];
    __shared__ int    jmin[NT];
    __shared__ int    freelist[NT];
    __shared__ int    s_nf;
    __shared__ unsigned long long s_K[2][4];   // per-warp argmin slots (parity)
    __shared__ int                s_J[2][4];

    const double DINF = __longlong_as_double(0x7FF0000000000000LL);
    const float  FINF = __int_as_float(0x7F800000);
    const unsigned FULL = 0xffffffffu;

    // ---- global init (all 128 threads) ----
    col4row[tid] = -1;
    for (int j = tid; j < NQ; j += 128) { v[j] = 0.0; row4col[j] = -1; }
    __syncthreads();

    // ---- row reduction: u[i] = min_j c[i][j] (exact in f32) ----
    for (int r = wid; r < NT; r += 4) {
        const float* __restrict__ row = ct + (size_t)r * NQ;
        float m = FINF; int mj = 0;
        for (int j = lane; j < NQ; j += 32) {
            const float c = __ldg(row + j);
            if (c < m) { m = c; mj = j; }
        }
#pragma unroll
        for (int off = 16; off > 0; off >>= 1) {
            const float ov = __shfl_down_sync(FULL, m, off);
            const int   oj = __shfl_down_sync(FULL, mj, off);
            if (ov < m || (ov == m && oj < mj)) { m = ov; mj = oj; }
        }
        if (lane == 0) { u[r] = (double)m; jmin[r] = mj; }
    }
    __syncthreads();

    // ---- greedy zero-assignment + free-row list (thread 0) ----
    if (tid == 0) {
        int nf = 0;
        for (int i = 0; i < NT; i++) {
            const int j = jmin[i];
            if (row4col[j] < 0) { row4col[j] = i; col4row[i] = j; }
            else freelist[nf++] = i;
        }
        s_nf = nf;
    }
    __syncthreads();

    // ======== LAPJV augmenting row reduction (warp 0 only) ========
    if (wid == 0) {
        const int nf = s_nf;
        int li = 1;
        int i = (nf > 0) ? freelist[0] : -1;
        int steps = 0;
        const int cap = 4 * nf + 8;
        while (i >= 0 && steps < cap) {
            steps++;
            const float* __restrict__ crow = ct + (size_t)i * NQ;
            double m1 = DINF, m2 = DINF;
            int j1 = -1, j2 = -1;
#pragma unroll
            for (int k = 0; k < NCPL; k++) {
                const int j = (k << 5) + lane;
                if (j < NQ) {
                    const double rc = (double)__ldg(crow + j) - v[j];
                    if (rc < m1)      { m2 = m1; j2 = j1; m1 = rc; j1 = j; }
                    else if (rc < m2) { m2 = rc; j2 = j; }
                }
            }
#pragma unroll
            for (int off = 16; off > 0; off >>= 1) {
                const double om1 = __shfl_down_sync(FULL, m1, off);
                const double om2 = __shfl_down_sync(FULL, m2, off);
                const int    oj1 = __shfl_down_sync(FULL, j1, off);
                const int    oj2 = __shfl_down_sync(FULL, j2, off);
                if (om1 < m1) {
                    if (m1 < om2) { m2 = m1;  j2 = j1;  }
                    else          { m2 = om2; j2 = oj2; }
                    m1 = om1; j1 = oj1;
                } else if (om1 < m2) { m2 = om1; j2 = oj1; }
            }
            int nexti = -1;
            if (lane == 0) {
                const double u1 = m1, u2 = m2;
                int jj = j1;
                u[i] = u2;
                if (u1 < u2)                            v[jj] -= (u2 - u1);
                else if (row4col[jj] >= 0 && j2 >= 0)   jj = j2;   // u1 == u2
                const int kk = row4col[jj];
                row4col[jj] = i; col4row[i] = jj;
                if (kk >= 0) { col4row[kk] = -1; nexti = kk; }
                else         { nexti = (li < nf) ? freelist[li++] : -1; }
            }
            nexti = __shfl_sync(FULL, nexti, 0);
            i = nexti;
            __syncwarp();
        }
    }
    __syncthreads();

    // ======== Dijkstra augmenting phases (4-warp sweep) ========
    for (int cur = 0; cur < NT; cur++) {
        if (col4row[cur] >= 0) continue;   // uniform across block

        // per-phase packed snapshot (row4col and u are phase-stable)
        for (int j = tid; j < NQ; j += 128) {
            const int r = row4col[j];
            pk[j] = make_ulonglong2(
                (unsigned long long)__double_as_longlong(r >= 0 ? u[r] : 0.0),
                (unsigned long long)(long long)r);
        }
        // per-thread register caches over its NCPT columns (j = k*128 + tid):
        //   vv[k] : v[j] (phase-stable)
        //   kp[k] : key of shifted value (c + w) that produced current spc
        //   ck[k] : key of the exact spc value (argmin operand)
        double vv[NCPT];
        unsigned long long kp[NCPT];
        unsigned long long ck[NCPT];
#pragma unroll
        for (int k = 0; k < NCPT; k++) {
            const int j = (k << 7) + tid;
            vv[k] = (j < NQ) ? v[j] : 0.0;
            kp[k] = ~0ULL;
            ck[k] = ~0ULL;
        }
        unsigned ms = (tid < 116) ? 0u : 0x8u;   // k=3 invalid for tid >= 116
        int cnt = 0;
        int sink = -1;
        double minv = 0.0;
        double w = -u[cur];          // first expansion: i = cur
        int i = cur;
        int it = 0;
        __syncthreads();             // pk + register state ready

        while (sink < 0) {
            const float* __restrict__ drow = ct + (size_t)i * NQ;

            // sweep own columns (deferred-vv improve test)
            unsigned long long bk = ~0ULL; int bj = NQ;
#pragma unroll
            for (int k = 0; k < NCPT; k++) {
                if (!((ms >> k) & 1u)) {
                    const int j = (k << 7) + tid;
                    const double rp = (double)__ldg(drow + j) + w;   // 1 DADD
                    const unsigned long long keyp = dkey(rp);
                    if (keyp < kp[k]) {
                        kp[k] = keyp;
                        ck[k] = dkey(rp - vv[k]);    // exact spc key (rare)
                        path[j] = i;
                    }
                    const unsigned long long c = ck[k];
                    if (c < bk) { bk = c; bj = j; }  // k ascending -> j ascending
                }
            }

            // per-warp exact 64-bit argmin (tie -> smaller j)
            const unsigned hi = (unsigned)(bk >> 32);
            const unsigned lo = (unsigned)bk;
            const unsigned mh = __reduce_min_sync(FULL, hi);
            const unsigned bal1 = __ballot_sync(FULL, hi == mh);
            unsigned long long Kw; int Jl;
            if (__popc(bal1) == 1) {
                const int src = __ffs(bal1) - 1;
                Jl = __shfl_sync(FULL, bj, src);
                Kw = ((unsigned long long)mh << 32) | __shfl_sync(FULL, lo, src);
            } else {
                const unsigned ml = __reduce_min_sync(FULL, (hi == mh) ? lo : 0xffffffffu);
                const bool win = (hi == mh) && (lo == ml);
                const unsigned bal2 = __ballot_sync(FULL, win);
                if (__popc(bal2) == 1) {
                    Jl = __shfl_sync(FULL, bj, __ffs(bal2) - 1);
                } else {
                    Jl = (int)__reduce_min_sync(FULL, win ? (unsigned)bj : 0xffffffffu);
                }
                Kw = ((unsigned long long)mh << 32) | ml;
            }
            const int p = it & 1;
            if (lane == 0) { s_K[p][wid] = Kw; s_J[p][wid] = Jl; }
            __syncthreads();

            // deterministic 4-slot merge (identical in every thread)
            unsigned long long K = s_K[p][0]; int Jw = s_J[p][0];
#pragma unroll
            for (int ww = 1; ww < 4; ww++) {
                const unsigned long long Ko = s_K[p][ww];
                const int Jo = s_J[p][ww];
                if (Ko < K || (Ko == K && Jo < Jw)) { K = Ko; Jw = Jo; }
            }
            minv = kinv(K);                     // bit-exact spc[Jw]

            const ulonglong2 pp = pk[Jw];       // phase-stable broadcast LDS
            const int r4c = (int)(long long)pp.y;
            if (tid == 0) { clist[cnt] = Jw; cdist[cnt] = minv; }
            cnt++;
            if (tid == (Jw & 127)) ms |= 1u << (Jw >> 7);   // settle own column
            if (r4c < 0) { sink = Jw; }
            else { i = r4c; w = minv - __longlong_as_double((long long)pp.x); }
            it++;
        }

        __syncthreads();   // publish clist/cdist/path before cross-thread reads

        // dual updates from the compact settle list (exact JV formulas)
        for (int t = tid; t < cnt; t += 128) {
            const int    J = clist[t];
            const double d = cdist[t];
            v[J] -= minv - d;
            const int r = (int)(long long)pk[J].y;
            if (r >= 0) u[r] += minv - d;
        }
        if (tid == 0) u[cur] += minv;
        __syncthreads();

        // augment along the alternating path (thread 0)
        if (tid == 0) {
            int j = sink;
            while (true) {
                const int ii = path[j];
                row4col[j] = ii;
                const int nj = col4row[ii];
                col4row[ii] = j;
                j = nj;
                if (ii == cur) break;
            }
        }
        __syncthreads();
    }

    // ---- emit row_ind / col_ind in sorted-by-query order ----
    if (out_size >= BATCH * NQ * NT + 2 * BATCH * NT && tid < NT) {
        float* rows = out + (size_t)BATCH * NQ * NT;
        float* cols = rows + BATCH * NT;
        const int q = col4row[tid];
        int rank = 0;
#pragma unroll 8
        for (int tt = 0; tt < NT; tt++) rank += (col4row[tt] < q) ? 1 : 0;
        rows[b * NT + rank] = (float)q;    // row_ind: sorted query indices
        cols[b * NT + rank] = (float)tid;  // col_ind: target for that query
    }
}

// ---------------------------------------------------------------------------
extern "C" void kernel_launch(void* const* d_in, const int* in_sizes, int n_in,
                              void* d_out, int out_size)
{
    const float* pred_boxes = (const float*)d_in[0];   // (16, 500, 4)
    const float* pred_kpts  = (const float*)d_in[1];   // (16, 500, 17, 2)
    const float* tgt_boxes  = (const float*)d_in[2];   // (16, 128, 4)
    const float* tgt_kpts   = (const float*)d_in[3];   // (16, 128, 17, 2)
    float* out = (float*)d_out;

    dim3 cgrid(NQ / QT, BATCH);
    cost_kernel<<<cgrid, 128>>>(pred_boxes, pred_kpts, tgt_boxes, tgt_kpts, out);
    lsa_kernel<<<BATCH, 128>>>(out, out_size);
}

// round 17
// speedup vs baseline: 1.0505x; 1.0505x over previous
#include <cuda_runtime.h>
#include <math.h>

// Problem dims (fixed by the reference)
#define BATCH 16
#define NQ    500   // queries (pred) = columns
#define NT    128   // targets       = rows
#define KPT   34    // 17 keypoints * 2
#define NCPL  16    // columns per lane: ceil(500/32)
#define QT    4     // queries per cost block (500 = 125 * 4)

// Transposed cost scratch: [b][target n][query q], f32 only.
__device__ float g_ct[BATCH * NT * NQ];

// ---------------------------------------------------------------------------
// Kernel 1: cost matrix (passing R14/R15 version, unchanged).
// ---------------------------------------------------------------------------
__global__ __launch_bounds__(128) void cost_kernel(
    const float* __restrict__ pred_boxes,   // (B, Q, 4)  cxcywh
    const float* __restrict__ pred_kpts,    // (B, Q, 17, 2)
    const float* __restrict__ tgt_boxes,    // (B, N, 4)  cxcywh
    const float* __restrict__ tgt_kpts,     // (B, N, 17, 2)
    float* __restrict__ C)                  // (B, Q, N)
{
    const int q0 = blockIdx.x * QT;
    const int b  = blockIdx.y;
    const int n  = threadIdx.x;

    __shared__ float s_pk[QT][KPT];
    __shared__ float s_pb[QT][4];
    for (int x = n; x < QT * KPT; x += 128)
        s_pk[x / KPT][x % KPT] = pred_kpts[(size_t)(b * NQ + q0 + x / KPT) * KPT + (x % KPT)];
    if (n < QT * 4)
        s_pb[n >> 2][n & 3] = pred_boxes[(b * NQ + q0 + (n >> 2)) * 4 + (n & 3)];
    __syncthreads();

    const float* tbn = tgt_boxes + (b * NT + n) * 4;
    const float t0 = __ldg(tbn + 0), t1 = __ldg(tbn + 1);
    const float t2 = __ldg(tbn + 2), t3 = __ldg(tbn + 3);
    float tx0 = t0 - 0.5f * t2, ty0 = t1 - 0.5f * t3;
    float tx1 = t0 + 0.5f * t2, ty1 = t1 + 0.5f * t3;
    tx1 = fmaxf(tx1, tx0 + 1e-4f);
    ty1 = fmaxf(ty1, ty0 + 1e-4f);
    const float at = (tx1 - tx0) * (ty1 - ty0);

    float tk[KPT];
    {
        const float2* tk2 = (const float2*)(tgt_kpts + (size_t)(b * NT + n) * KPT);
#pragma unroll
        for (int k = 0; k < KPT / 2; k++) {
            const float2 p = __ldg(tk2 + k);
            tk[2 * k] = p.x; tk[2 * k + 1] = p.y;
        }
    }

    float res[QT];
#pragma unroll
    for (int t = 0; t < QT; t++) {
        const float p0 = s_pb[t][0], p1 = s_pb[t][1], p2 = s_pb[t][2], p3 = s_pb[t][3];

        float cbbox = fabsf(p0 - t0) + fabsf(p1 - t1) + fabsf(p2 - t2) + fabsf(p3 - t3);

        float px0 = p0 - 0.5f * p2, py0 = p1 - 0.5f * p3;
        float px1 = p0 + 0.5f * p2, py1 = p1 + 0.5f * p3;
        px1 = fmaxf(px1, px0 + 1e-4f);
        py1 = fmaxf(py1, py0 + 1e-4f);

        const float ap = (px1 - px0) * (py1 - py0);

        const float iw = fmaxf(fminf(px1, tx1) - fmaxf(px0, tx0), 0.0f);
        const float ih = fmaxf(fminf(py1, ty1) - fmaxf(py0, ty0), 0.0f);
        const float inter = iw * ih;
        const float uni = ap + at - inter;
        const float iou = inter / uni;

        const float ew = fmaxf(fmaxf(px1, tx1) - fminf(px0, tx0), 0.0f);
        const float eh = fmaxf(fmaxf(py1, ty1) - fminf(py0, ty0), 0.0f);
        const float enc = ew * eh;
        const float giou = iou - (enc - uni) / enc;

        float ckpt = 0.0f;
#pragma unroll
        for (int k = 0; k < KPT; k++) ckpt += fabsf(s_pk[t][k] - tk[k]);

        const float cost = 5.0f * cbbox - 2.0f * giou + 1.0f * ckpt;
        res[t] = cost;
        C[(size_t)(b * NQ + q0 + t) * NT + n] = cost;
    }
    *(float4*)(g_ct + (size_t)(b * NT + n) * NQ + q0) =
        make_float4(res[0], res[1], res[2], res[3]);
}

// Monotone bijection double <-> uint64 (order-preserving, exact).
__device__ __forceinline__ unsigned long long dkey(double x) {
    const long long b = __double_as_longlong(x);
    return (unsigned long long)b ^ ((b < 0) ? 0xFFFFFFFFFFFFFFFFULL
                                             : 0x8000000000000000ULL);
}
__device__ __forceinline__ double kinv(unsigned long long k) {
    const long long b = (k & 0x8000000000000000ULL)
                      ? (long long)(k ^ 0x8000000000000000ULL)
                      : ~(long long)k;
    return __longlong_as_double(b);
}

// ---------------------------------------------------------------------------
// Kernel 2: exact JV LSA — R15 single-warp structure. This round the sweep's
// compare machinery uses native double compares (DSETP) everywhere; the
// integer key is computed ONCE per lane per iteration for the redux argmin.
// Total order identical (exact bijection), tie-break semantics unchanged.
// ---------------------------------------------------------------------------
__global__ __launch_bounds__(128) void lsa_kernel(float* __restrict__ out, int out_size)
{
    const int b    = blockIdx.x;
    const int tid  = threadIdx.x;
    const int lane = tid & 31;
    const int wid  = tid >> 5;
    const float* __restrict__ ct = g_ct + (size_t)b * NT * NQ;

    __shared__ double v[NQ];
    __shared__ double u[NT];
    __shared__ double cdist[NQ];
    __shared__ ulonglong2 pk[NQ];       // per-phase: {u[row4col[j]] bits, row4col[j]}
    __shared__ int    clist[NQ];
    __shared__ int    path[NQ];
    __shared__ int    row4col[NQ];
    __shared__ int    col4row[NT];
    __shared__ int    jmin[NT];
    __shared__ int    freelist[NT];
    __shared__ int    s_nf;

    const double DINF = __longlong_as_double(0x7FF0000000000000LL);
    const float  FINF = __int_as_float(0x7F800000);
    const unsigned FULL = 0xffffffffu;

    // ---- global init (all 128 threads) ----
    col4row[tid] = -1;
    for (int j = tid; j < NQ; j += 128) { v[j] = 0.0; row4col[j] = -1; }
    __syncthreads();

    // ---- row reduction: u[i] = min_j c[i][j] (exact in f32) ----
    for (int r = wid; r < NT; r += 4) {
        const float* __restrict__ row = ct + (size_t)r * NQ;
        float m = FINF; int mj = 0;
        for (int j = lane; j < NQ; j += 32) {
            const float c = __ldg(row + j);
            if (c < m) { m = c; mj = j; }
        }
#pragma unroll
        for (int off = 16; off > 0; off >>= 1) {
            const float ov = __shfl_down_sync(FULL, m, off);
            const int   oj = __shfl_down_sync(FULL, mj, off);
            if (ov < m || (ov == m && oj < mj)) { m = ov; mj = oj; }
        }
        if (lane == 0) { u[r] = (double)m; jmin[r] = mj; }
    }
    __syncthreads();

    // ---- greedy zero-assignment + free-row list (thread 0) ----
    if (tid == 0) {
        int nf = 0;
        for (int i = 0; i < NT; i++) {
            const int j = jmin[i];
            if (row4col[j] < 0) { row4col[j] = i; col4row[i] = j; }
            else freelist[nf++] = i;
        }
        s_nf = nf;
    }
    __syncthreads();

    if (wid != 0) return;   // warp 0 carries on alone; no __syncthreads below

    // ======== LAPJV augmenting row reduction (warp-cooperative) ========
    {
        const int nf = s_nf;
        int li = 1;
        int i = (nf > 0) ? freelist[0] : -1;
        int steps = 0;
        const int cap = 4 * nf + 8;
        while (i >= 0 && steps < cap) {
            steps++;
            const float* __restrict__ crow = ct + (size_t)i * NQ;
            double m1 = DINF, m2 = DINF;
            int j1 = -1, j2 = -1;
#pragma unroll
            for (int k = 0; k < NCPL; k++) {
                const int j = (k << 5) + lane;
                if (j < NQ) {
                    const double rc = (double)__ldg(crow + j) - v[j];
                    if (rc < m1)      { m2 = m1; j2 = j1; m1 = rc; j1 = j; }
                    else if (rc < m2) { m2 = rc; j2 = j; }
                }
            }
#pragma unroll
            for (int off = 16; off > 0; off >>= 1) {
                const double om1 = __shfl_down_sync(FULL, m1, off);
                const double om2 = __shfl_down_sync(FULL, m2, off);
                const int    oj1 = __shfl_down_sync(FULL, j1, off);
                const int    oj2 = __shfl_down_sync(FULL, j2, off);
                if (om1 < m1) {
                    if (m1 < om2) { m2 = m1;  j2 = j1;  }
                    else          { m2 = om2; j2 = oj2; }
                    m1 = om1; j1 = oj1;
                } else if (om1 < m2) { m2 = om1; j2 = oj1; }
            }
            int nexti = -1;
            if (lane == 0) {
                const double u1 = m1, u2 = m2;
                int jj = j1;
                u[i] = u2;
                if (u1 < u2)                            v[jj] -= (u2 - u1);
                else if (row4col[jj] >= 0 && j2 >= 0)   jj = j2;   // u1 == u2
                const int kk = row4col[jj];
                row4col[jj] = i; col4row[i] = jj;
                if (kk >= 0) { col4row[kk] = -1; nexti = kk; }
                else         { nexti = (li < nf) ? freelist[li++] : -1; }
            }
            nexti = __shfl_sync(FULL, nexti, 0);
            i = nexti;
            __syncwarp();
        }
    }

    // ======== Dijkstra augmenting phases (single warp, register state) ======
    for (int cur = 0; cur < NT; cur++) {
        if (col4row[cur] >= 0) continue;

        // per-phase packed snapshot (row4col and u are phase-stable)
        for (int j = lane; j < NQ; j += 32) {
            const int r = row4col[j];
            pk[j] = make_ulonglong2(
                (unsigned long long)__double_as_longlong(r >= 0 ? u[r] : 0.0),
                (unsigned long long)(long long)r);
        }
        // per-lane register caches (all doubles; compares are DSETP):
        //   vv[k]  : v[j] (phase-stable)
        //   rpm[k] : min shifted value (c + w) seen so far (improve test)
        //   spv[k] : exact spc value (argmin operand)
        double vv[NCPL], rpm[NCPL], spv[NCPL];
#pragma unroll
        for (int k = 0; k < NCPL; k++) {
            const int j = (k << 5) + lane;
            vv[k]  = (j < NQ) ? v[j] : 0.0;
            rpm[k] = DINF;
            spv[k] = DINF;
        }
        unsigned ms = (lane < 20) ? 0u : 0x8000u;   // k=15 invalid for lane>=20
        int cnt = 0;
        int sink = -1;
        double minv = 0.0;
        double w = -u[cur];          // first expansion: i = cur
        int i = cur;
        __syncwarp();                // pk visible

        while (sink < 0) {
            const float* __restrict__ drow = ct + (size_t)i * NQ;

            // 4 independent accumulator chains on native doubles
            double D0 = DINF, D1 = DINF, D2 = DINF, D3 = DINF;
            int J0 = NQ, J1 = NQ, J2 = NQ, J3 = NQ;
#pragma unroll
            for (int k = 0; k < NCPL; k++) {
                const int j = (k << 5) + lane;
                if (!((ms >> k) & 1u)) {
                    const double rp = (double)__ldg(drow + j) + w;   // 1 DADD
                    if (rp < rpm[k]) {               // improve test: 1 DSETP
                        rpm[k] = rp;
                        spv[k] = rp - vv[k];         // exact spc (DADD, rare)
                        path[j] = i;
                    }
                    const double d = spv[k];
                    switch (k & 3) {                 // 1 DSETP + selects
                        case 0: if (d < D0) { D0 = d; J0 = j; } break;
                        case 1: if (d < D1) { D1 = d; J1 = j; } break;
                        case 2: if (d < D2) { D2 = d; J2 = j; } break;
                        default:if (d < D3) { D3 = d; J3 = j; } break;
                    }
                }
            }
            // merge 4 accumulators (tie -> smaller j; within each, first-min kept)
            double D = D0; int J = J0;
            if (D1 < D || (D1 == D && J1 < J)) { D = D1; J = J1; }
            if (D2 < D || (D2 == D && J2 < J)) { D = D2; J = J2; }
            if (D3 < D || (D3 == D && J3 < J)) { D = D3; J = J3; }

            // key conversion ONCE per lane; exact redux/ballot argmin as before
            const unsigned long long K = dkey(D);
            const unsigned hi = (unsigned)(K >> 32);
            const unsigned lo = (unsigned)K;
            const unsigned mh = __reduce_min_sync(FULL, hi);
            const unsigned bal1 = __ballot_sync(FULL, hi == mh);
            int Jw; unsigned mlv;
            if (__popc(bal1) == 1) {
                const int src = __ffs(bal1) - 1;
                Jw  = __shfl_sync(FULL, J, src);
                mlv = __shfl_sync(FULL, lo, src);
            } else {
                const unsigned ml = __reduce_min_sync(FULL, (hi == mh) ? lo : 0xffffffffu);
                const bool win = (hi == mh) && (lo == ml);
                const unsigned bal2 = __ballot_sync(FULL, win);
                if (__popc(bal2) == 1) {
                    Jw = __shfl_sync(FULL, J, __ffs(bal2) - 1);
                } else {
                    Jw = (int)__reduce_min_sync(FULL, win ? (unsigned)J : 0xffffffffu);
                }
                mlv = ml;
            }
            minv = kinv(((unsigned long long)mh << 32) | mlv);   // bit-exact spc[Jw]

            // one LDS.128: {u[row4col[Jw]], row4col[Jw]} (phase-stable snapshot)
            const ulonglong2 p = pk[Jw];
            const int r4c = (int)(long long)p.y;
            if (lane == 0) { clist[cnt] = Jw; cdist[cnt] = minv; }
            cnt++;
            if (lane == (Jw & 31)) ms |= 1u << (Jw >> 5);   // settle: owning lane masks
            if (r4c < 0) { sink = Jw; }
            else { i = r4c; w = minv - __longlong_as_double((long long)p.x); }
        }

        __syncwarp();   // publish clist/cdist/path before cross-lane reads

        // dual updates from the compact settle list (exact JV formulas)
        for (int t = lane; t < cnt; t += 32) {
            const int    J = clist[t];
            const double d = cdist[t];
            v[J] -= minv - d;
            const int r = (int)(long long)pk[J].y;
            if (r >= 0) u[r] += minv - d;
        }
        if (lane == 0) u[cur] += minv;
        __syncwarp();

        // augment along the alternating path (lane 0)
        if (lane == 0) {
            int j = sink;
            while (true) {
                const int ii = path[j];
                row4col[j] = ii;
                const int nj = col4row[ii];
                col4row[ii] = j;
                j = nj;
                if (ii == cur) break;
            }
        }
        __syncwarp();
    }

    // ---- emit row_ind / col_ind in sorted-by-query order ----
    if (out_size >= BATCH * NQ * NT + 2 * BATCH * NT) {
        float* rows = out + (size_t)BATCH * NQ * NT;
        float* cols = rows + BATCH * NT;
        for (int t = lane; t < NT; t += 32) {
            const int q = col4row[t];
            int rank = 0;
#pragma unroll 8
            for (int tt = 0; tt < NT; tt++) rank += (col4row[tt] < q) ? 1 : 0;
            rows[b * NT + rank] = (float)q;    // row_ind: sorted query indices
            cols[b * NT + rank] = (float)t;    // col_ind: target for that query
        }
    }
}

// ---------------------------------------------------------------------------
extern "C" void kernel_launch(void* const* d_in, const int* in_sizes, int n_in,
                              void* d_out, int out_size)
{
    const float* pred_boxes = (const float*)d_in[0];   // (16, 500, 4)
    const float* pred_kpts  = (const float*)d_in[1];   // (16, 500, 17, 2)
    const float* tgt_boxes  = (const float*)d_in[2];   // (16, 128, 4)
    const float* tgt_kpts   = (const float*)d_in[3];   // (16, 128, 17, 2)
    float* out = (float*)d_out;

    dim3 cgrid(NQ / QT, BATCH);
    cost_kernel<<<cgrid, 128>>>(pred_boxes, pred_kpts, tgt_boxes, tgt_kpts, out);
    lsa_kernel<<<BATCH, 128>>>(out, out_size);
}